// round 7
// baseline (speedup 1.0000x reference)
#include <cuda_runtime.h>

// ---------------------------------------------------------------------------
// MoE router, round 7: split-K(4) FFMA2 GEMM, 1.0 B/MAC, 2 CTAs/SM.
//   grid = 64 token-tiles x 4 K-quarters, 256 thr/CTA, launch_bounds(256,2).
//   Per thread: 8 tok x 8 exp (f32x2 expert pairs). Register-dieted addressing.
//   Partials -> 16MB scratch; 4th-arriving CTA per tile sums + epilogue.
// Output f32: [0,32768) indices, [32768,65536) weights, [65536] aux.
// ---------------------------------------------------------------------------

#define TOKENS   16384
#define DDIM     2048
#define NEXP     64
#define BM       256
#define BK       16
#define KSPLIT   4
#define KPART    (DDIM / KSPLIT)    // 512
#define NSLAB    (KPART / BK)       // 32
#define NTILE    (TOKENS / BM)      // 64
#define NTHR     256
#define XSTR     20                 // x row stride (floats) = 80 B
#define WSTR     96                 // swizzled w row stride (floats)
#define LSTR     68                 // logits row stride (272 B, 16B-aligned)
#define XBUFB    (BM * XSTR * 4)    // bytes per x buffer = 20480
#define WGT_OFF  (2 * TOKENS)
#define AUX_OFF  (4 * TOKENS)
#define AUX_W    0.01f

typedef unsigned long long ull;

__device__ alignas(16) float g_part[KSPLIT][NTILE][BM][NEXP];   // 16 MB partials
__device__ int      g_tile_cnt[NTILE];
__device__ float    g_probsum[NEXP];
__device__ int      g_cnt[NEXP];
__device__ unsigned g_arrived;

__device__ __forceinline__ void fma2(ull& d, ull a, ull b) {
    asm("fma.rn.f32x2 %0, %1, %2, %0;" : "+l"(d) : "l"(a), "l"(b));
}
__device__ __forceinline__ ull dup2(float v) {
    ull r;
    asm("mov.b64 %0, {%1, %1};" : "=l"(r) : "f"(v));
    return r;
}
__device__ __forceinline__ unsigned su32(const void* p) {
    return (unsigned)__cvta_generic_to_shared(p);
}
__device__ __forceinline__ void cp16(unsigned dst, const float* src) {
    asm volatile("cp.async.cg.shared.global [%0], [%1], 16;" :: "r"(dst), "l"(src));
}

struct Smem {
    union {
        struct {
            float x[2][BM][XSTR];     // 40960 B (cp.async target, row-major)
            float w[2][BK][WSTR];     // 12288 B (swizzled expert pairs)
        } ml;
        struct { float logits[BM][LSTR]; } ep;   // 69632 B
    } u;
    float tmax[BM];
    float tinv[BM];
    int   scnt[NEXP];
    float red[NEXP];
    int   flag;
};

__global__ void __launch_bounds__(NTHR, 2)
moe_router(const float* __restrict__ X, const float* __restrict__ W,
           float* __restrict__ out) {
    extern __shared__ char raw[];
    Smem& s = *reinterpret_cast<Smem*>(raw);

    const int tid  = threadIdx.x;
    const int tile = blockIdx.x >> 2;
    const int kh   = blockIdx.x & 3;
    const int T0   = tile * BM;
    const int Kb   = kh * KPART;

    // thread tile: tokens {ty + 32j, j=0..7} x experts [8tx, 8tx+8)
    const int tx = tid & 7;
    const int ty = tid >> 3;
    const int e0 = tx * 8;
    const int wf = 12 * tx;            // swizzled float offset of 4 expert pairs

    // x cp.async base: chunk p adds 64 rows -> +64*DDIM floats gmem, +64*80B smem
    const int row0 = tid >> 2;         // 0..63
    const int cc   = (tid & 3) << 2;
    const float* xbase = X + (size_t)(T0 + row0) * DDIM + Kb + cc;
    const unsigned xd0 = su32(&s.u.ml.x[0][row0][cc]);

    // w map: expert we, 4 consecutive k's; swizzled store index
    const int we  = tid & 63;
    const int wk  = (tid >> 6) * 4;
    const int wsi = we + 4 * (we >> 3);
    const float* wsrc = W + (size_t)we * DDIM + Kb + wk;

    ull acc[8][4];
#pragma unroll
    for (int j = 0; j < 8; ++j)
#pragma unroll
        for (int i = 0; i < 4; ++i) acc[j][i] = 0ull;

    // --- prologue: slab 0 ---
#pragma unroll
    for (int p = 0; p < 4; ++p)
        cp16(xd0 + p * (64 * XSTR * 4), xbase + p * (64 * DDIM));
    asm volatile("cp.async.commit_group;" ::: "memory");
    {
        float4 wl = *(const float4*)wsrc;
        s.u.ml.w[0][wk + 0][wsi] = wl.x;
        s.u.ml.w[0][wk + 1][wsi] = wl.y;
        s.u.ml.w[0][wk + 2][wsi] = wl.z;
        s.u.ml.w[0][wk + 3][wsi] = wl.w;
    }
    asm volatile("cp.async.wait_group 0;" ::: "memory");
    __syncthreads();

    // --- mainloop over 32 double-buffered K-slabs ---
    float4 wl;
    for (int it = 0; it < NSLAB; ++it) {
        const int buf  = it & 1;
        const int nbuf = buf ^ 1;
        if (it + 1 < NSLAB) {
            const int K0 = (it + 1) * BK;
#pragma unroll
            for (int p = 0; p < 4; ++p)
                cp16(xd0 + nbuf * XBUFB + p * (64 * XSTR * 4),
                     xbase + K0 + p * (64 * DDIM));
            asm volatile("cp.async.commit_group;" ::: "memory");
            wl = *(const float4*)(wsrc + K0);
        }

#pragma unroll
        for (int kk = 0; kk < BK / 2; ++kk) {
            float2 xv[8];
#pragma unroll
            for (int j = 0; j < 8; ++j)
                xv[j] = *(const float2*)&s.u.ml.x[buf][ty + 32 * j][2 * kk];
#pragma unroll
            for (int h = 0; h < 2; ++h) {
                const float* wrow = s.u.ml.w[buf][2 * kk + h];
                ulonglong2 wA = *(const ulonglong2*)(wrow + wf);
                ulonglong2 wB = *(const ulonglong2*)(wrow + wf + 4);
#pragma unroll
                for (int j = 0; j < 8; ++j) {
                    ull xd = dup2(h ? xv[j].y : xv[j].x);
                    fma2(acc[j][0], xd, wA.x);
                    fma2(acc[j][1], xd, wA.y);
                    fma2(acc[j][2], xd, wB.x);
                    fma2(acc[j][3], xd, wB.y);
                }
            }
        }

        if (it + 1 < NSLAB) {
            s.u.ml.w[nbuf][wk + 0][wsi] = wl.x;
            s.u.ml.w[nbuf][wk + 1][wsi] = wl.y;
            s.u.ml.w[nbuf][wk + 2][wsi] = wl.z;
            s.u.ml.w[nbuf][wk + 3][wsi] = wl.w;
            asm volatile("cp.async.wait_group 0;" ::: "memory");
        }
        __syncthreads();
    }

    // --- write partial logits (deterministic: fixed addend count per logit) ---
#pragma unroll
    for (int j = 0; j < 8; ++j) {
        const int tok = ty + 32 * j;
        ulonglong2* dst = (ulonglong2*)&g_part[kh][tile][tok][e0];
        dst[0] = make_ulonglong2(acc[j][0], acc[j][1]);
        dst[1] = make_ulonglong2(acc[j][2], acc[j][3]);
    }
    __threadfence();
    if (tid == 0) {
        int old = atomicAdd(&g_tile_cnt[tile], 1);
        s.flag = (old == KSPLIT - 1);
    }
    __syncthreads();
    if (!s.flag) return;            // first KSPLIT-1 CTAs of the tile exit
    __threadfence();

    // ===================== epilogue (last CTA of the tile) =====================
    if (tid == 0) g_tile_cnt[tile] = 0;       // reset for graph replay
    if (tid < NEXP) s.scnt[tid] = 0;
    __syncthreads();

    // combine K-quarters; keep logits in regs AND mirror to smem for phase 2
    const int t = tid;
    float lg[NEXP];
    {
#pragma unroll
        for (int c = 0; c < NEXP / 4; ++c) {
            float4 a = __ldcg((const float4*)&g_part[0][tile][t][4 * c]);
#pragma unroll
            for (int q = 1; q < KSPLIT; ++q) {
                float4 b = __ldcg((const float4*)&g_part[q][tile][t][4 * c]);
                a.x += b.x; a.y += b.y; a.z += b.z; a.w += b.w;
            }
            lg[4 * c + 0] = a.x; lg[4 * c + 1] = a.y;
            lg[4 * c + 2] = a.z; lg[4 * c + 3] = a.w;
            *(float4*)&s.u.ep.logits[t][4 * c] = a;
        }
    }

    // top-2 (stable: strict >, lowest index wins ties) + full-softmax normalizer
    {
        float m1 = -3.4e38f, m2 = -3.4e38f;
        int   i1 = 0, i2 = 0;
#pragma unroll
        for (int e = 0; e < NEXP; ++e) {
            float l = lg[e];
            if (l > m1) { m2 = m1; i2 = i1; m1 = l; i1 = e; }
            else if (l > m2) { m2 = l; i2 = e; }
        }
        float sum = 0.0f;
#pragma unroll
        for (int e = 0; e < NEXP; ++e) sum += __expf(lg[e] - m1);
        s.tmax[t] = m1;
        s.tinv[t] = 1.0f / sum;

        const int T = T0 + t;
        float d  = expf(m2 - m1);
        float w1 = 1.0f / (1.0f + d);
        out[2 * T + 0] = (float)i1;
        out[2 * T + 1] = (float)i2;
        out[WGT_OFF + 2 * T + 0] = w1;
        out[WGT_OFF + 2 * T + 1] = d * w1;

        atomicAdd(&s.scnt[i1], 1);
    }
    __syncthreads();

    // per-expert probability partials: 4 row-groups x 64 experts x 64 tokens
    {
        const int g  = tid >> 6;
        const int e  = tid & 63;
        const int tb = g * 64;
        float partial = 0.0f;
#pragma unroll 8
        for (int tt = tb; tt < tb + 64; ++tt)
            partial += __expf(s.u.ep.logits[tt][e] - s.tmax[tt]) * s.tinv[tt];
        atomicAdd(&g_probsum[e], partial);
    }
    if (tid < NEXP) atomicAdd(&g_cnt[tid], s.scnt[tid]);

    // --- global finalize: last epilogue CTA computes aux loss + resets ---
    __threadfence();
    if (tid == 0) {
        unsigned old = atomicAdd(&g_arrived, 1u);
        s.flag = (old == NTILE - 1);
    }
    __syncthreads();
    if (!s.flag) return;
    __threadfence();

    if (tid < NEXP) {
        float p = __ldcg(&g_probsum[tid]);
        int   c = __ldcg(&g_cnt[tid]);
        s.red[tid] = p * (float)c;
    }
    __syncthreads();
    if (tid == 0) {
        float sacc = 0.0f;
#pragma unroll
        for (int i = 0; i < NEXP; ++i) sacc += s.red[i];
        const float invN = 1.0f / (float)TOKENS;
        out[AUX_OFF] = (float)NEXP * sacc * invN * invN * AUX_W;
        g_arrived = 0u;
    }
    if (tid < NEXP) { g_probsum[tid] = 0.0f; g_cnt[tid] = 0; }
}

extern "C" void kernel_launch(void* const* d_in, const int* in_sizes, int n_in,
                              void* d_out, int out_size) {
    const float* X = (const float*)d_in[0];   // [4,4096,2048] f32
    const float* W = (const float*)d_in[1];   // [64,2048] f32
    float* out = (float*)d_out;               // 65537 f32

    static_assert(sizeof(Smem) <= 80 * 1024, "smem");
    cudaFuncSetAttribute(moe_router, cudaFuncAttributeMaxDynamicSharedMemorySize,
                         (int)sizeof(Smem));
    moe_router<<<NTILE * KSPLIT, NTHR, sizeof(Smem)>>>(X, W, out);
}

// round 8
// speedup vs baseline: 1.0036x; 1.0036x over previous
#include <cuda_runtime.h>

// ---------------------------------------------------------------------------
// MoE router, round 8: split-K(2) FFMA2 GEMM, 512 thr/CTA, 16 warps/SM.
//   grid = 64 token-tiles x 2 K-halves. Per thread: 4 tok x 8 exp
//   (f32x2 expert-pair accumulators, 32 regs). BM=256, BK=16 double-buffered.
//   Partials -> 8MB scratch; 2nd-arriving CTA per tile sums + epilogue.
// Output f32: [0,32768) indices, [32768,65536) weights, [65536] aux.
// ---------------------------------------------------------------------------

#define TOKENS   16384
#define DDIM     2048
#define NEXP     64
#define BM       256
#define BK       16
#define KSPLIT   2
#define KPART    (DDIM / KSPLIT)    // 1024
#define NSLAB    (KPART / BK)       // 64
#define NTILE    (TOKENS / BM)      // 64
#define NTHR     512
#define XSTR     20                 // x row stride (floats) = 80 B
#define WSTR     96                 // swizzled w row stride (floats)
#define LSTR     68                 // logits row stride (272 B, 16B-aligned)
#define XBUFB    (BM * XSTR * 4)    // bytes per x buffer = 20480
#define WGT_OFF  (2 * TOKENS)
#define AUX_OFF  (4 * TOKENS)
#define AUX_W    0.01f

typedef unsigned long long ull;

__device__ alignas(16) float g_part[KSPLIT][NTILE][BM][NEXP];   // 8 MB partials
__device__ int      g_tile_cnt[NTILE];
__device__ float    g_probsum[NEXP];
__device__ int      g_cnt[NEXP];
__device__ unsigned g_arrived;

__device__ __forceinline__ void fma2(ull& d, ull a, ull b) {
    asm("fma.rn.f32x2 %0, %1, %2, %0;" : "+l"(d) : "l"(a), "l"(b));
}
__device__ __forceinline__ ull dup2(float v) {
    ull r;
    asm("mov.b64 %0, {%1, %1};" : "=l"(r) : "f"(v));
    return r;
}
__device__ __forceinline__ unsigned su32(const void* p) {
    return (unsigned)__cvta_generic_to_shared(p);
}
__device__ __forceinline__ void cp16(unsigned dst, const float* src) {
    asm volatile("cp.async.cg.shared.global [%0], [%1], 16;" :: "r"(dst), "l"(src));
}

struct Smem {
    union {
        struct {
            float x[2][BM][XSTR];     // 40960 B (cp.async target, row-major)
            float w[2][BK][WSTR];     // 12288 B (swizzled expert pairs)
        } ml;
        struct { float logits[BM][LSTR]; } ep;   // 69632 B
    } u;
    float tmax[BM];
    float tinv[BM];
    int   scnt[NEXP];
    float red[NEXP];
    int   flag;
};

__global__ void __launch_bounds__(NTHR, 1)
moe_router(const float* __restrict__ X, const float* __restrict__ W,
           float* __restrict__ out) {
    extern __shared__ char raw[];
    Smem& s = *reinterpret_cast<Smem*>(raw);

    const int tid  = threadIdx.x;
    const int tile = blockIdx.x >> 1;
    const int kh   = blockIdx.x & 1;
    const int T0   = tile * BM;
    const int Kb   = kh * KPART;

    // thread tile: tokens {ty + 64j, j=0..3} x experts [8tx, 8tx+8)
    const int tx = tid & 7;
    const int ty = tid >> 3;           // 0..63
    const int e0 = tx * 8;
    const int wf = 12 * tx;            // swizzled float offset of 4 expert pairs

    // x cp.async: 2 chunks of 16B; chunk p adds 128 rows
    const int row0 = tid >> 2;         // 0..127
    const int cc   = (tid & 3) << 2;
    const float* xbase = X + (size_t)(T0 + row0) * DDIM + Kb + cc;
    const unsigned xd0 = su32(&s.u.ml.x[0][row0][cc]);

    // w map: expert we, 2 consecutive k's; swizzled store index
    const int we  = tid & 63;
    const int wk  = (tid >> 6) * 2;    // 8 groups x 2 k = BK
    const int wsi = we + 4 * (we >> 3);
    const float* wsrc = W + (size_t)we * DDIM + Kb + wk;

    ull acc[4][4];
#pragma unroll
    for (int j = 0; j < 4; ++j)
#pragma unroll
        for (int i = 0; i < 4; ++i) acc[j][i] = 0ull;

    // --- prologue: slab 0 ---
#pragma unroll
    for (int p = 0; p < 2; ++p)
        cp16(xd0 + p * (128 * XSTR * 4), xbase + p * (128 * DDIM));
    asm volatile("cp.async.commit_group;" ::: "memory");
    {
        float2 wl = *(const float2*)wsrc;
        s.u.ml.w[0][wk + 0][wsi] = wl.x;
        s.u.ml.w[0][wk + 1][wsi] = wl.y;
    }
    asm volatile("cp.async.wait_group 0;" ::: "memory");
    __syncthreads();

    // --- mainloop over 64 double-buffered K-slabs ---
    float2 wl;
    for (int it = 0; it < NSLAB; ++it) {
        const int buf  = it & 1;
        const int nbuf = buf ^ 1;
        if (it + 1 < NSLAB) {
            const int K0 = (it + 1) * BK;
#pragma unroll
            for (int p = 0; p < 2; ++p)
                cp16(xd0 + nbuf * XBUFB + p * (128 * XSTR * 4),
                     xbase + K0 + p * (128 * DDIM));
            asm volatile("cp.async.commit_group;" ::: "memory");
            wl = *(const float2*)(wsrc + K0);
        }

#pragma unroll
        for (int kk = 0; kk < BK / 2; ++kk) {
            float2 xv[4];
#pragma unroll
            for (int j = 0; j < 4; ++j)
                xv[j] = *(const float2*)&s.u.ml.x[buf][ty + 64 * j][2 * kk];
#pragma unroll
            for (int h = 0; h < 2; ++h) {
                const float* wrow = s.u.ml.w[buf][2 * kk + h];
                ulonglong2 wA = *(const ulonglong2*)(wrow + wf);
                ulonglong2 wB = *(const ulonglong2*)(wrow + wf + 4);
#pragma unroll
                for (int j = 0; j < 4; ++j) {
                    ull xd = dup2(h ? xv[j].y : xv[j].x);
                    fma2(acc[j][0], xd, wA.x);
                    fma2(acc[j][1], xd, wA.y);
                    fma2(acc[j][2], xd, wB.x);
                    fma2(acc[j][3], xd, wB.y);
                }
            }
        }

        if (it + 1 < NSLAB) {
            s.u.ml.w[nbuf][wk + 0][wsi] = wl.x;
            s.u.ml.w[nbuf][wk + 1][wsi] = wl.y;
            asm volatile("cp.async.wait_group 0;" ::: "memory");
        }
        __syncthreads();
    }

    // --- write partial logits (deterministic: 2 addends per logit) ---
#pragma unroll
    for (int j = 0; j < 4; ++j) {
        const int tok = ty + 64 * j;
        ulonglong2* dst = (ulonglong2*)&g_part[kh][tile][tok][e0];
        dst[0] = make_ulonglong2(acc[j][0], acc[j][1]);
        dst[1] = make_ulonglong2(acc[j][2], acc[j][3]);
    }
    __threadfence();
    if (tid == 0) {
        int old = atomicAdd(&g_tile_cnt[tile], 1);
        s.flag = (old == KSPLIT - 1);
    }
    __syncthreads();
    if (!s.flag) return;            // first CTA of the pair exits
    __threadfence();

    // ===================== epilogue (second CTA of the tile) ====================
    if (tid == 0) g_tile_cnt[tile] = 0;       // reset for graph replay
    if (tid < NEXP) s.scnt[tid] = 0;
    __syncthreads();

    // combine K-halves; per-token work on threads 0..255
    if (tid < BM) {
        const int t = tid;
        float lg[NEXP];
#pragma unroll
        for (int c = 0; c < NEXP / 4; ++c) {
            float4 a = __ldcg((const float4*)&g_part[0][tile][t][4 * c]);
            float4 b = __ldcg((const float4*)&g_part[1][tile][t][4 * c]);
            a.x += b.x; a.y += b.y; a.z += b.z; a.w += b.w;
            lg[4 * c + 0] = a.x; lg[4 * c + 1] = a.y;
            lg[4 * c + 2] = a.z; lg[4 * c + 3] = a.w;
            *(float4*)&s.u.ep.logits[t][4 * c] = a;
        }

        // top-2 (stable: strict >, lowest index wins ties) + softmax normalizer
        float m1 = -3.4e38f, m2 = -3.4e38f;
        int   i1 = 0, i2 = 0;
#pragma unroll
        for (int e = 0; e < NEXP; ++e) {
            float l = lg[e];
            if (l > m1) { m2 = m1; i2 = i1; m1 = l; i1 = e; }
            else if (l > m2) { m2 = l; i2 = e; }
        }
        float sum = 0.0f;
#pragma unroll
        for (int e = 0; e < NEXP; ++e) sum += __expf(lg[e] - m1);
        s.tmax[t] = m1;
        s.tinv[t] = 1.0f / sum;

        const int T = T0 + t;
        float d  = expf(m2 - m1);
        float w1 = 1.0f / (1.0f + d);
        out[2 * T + 0] = (float)i1;
        out[2 * T + 1] = (float)i2;
        out[WGT_OFF + 2 * T + 0] = w1;
        out[WGT_OFF + 2 * T + 1] = d * w1;

        atomicAdd(&s.scnt[i1], 1);
    }
    __syncthreads();

    // per-expert probability partials: 8 row-groups x 64 experts x 32 tokens
    {
        const int g  = tid >> 6;          // 0..7
        const int e  = tid & 63;
        const int tb = g * 32;
        float partial = 0.0f;
#pragma unroll 8
        for (int tt = tb; tt < tb + 32; ++tt)
            partial += __expf(s.u.ep.logits[tt][e] - s.tmax[tt]) * s.tinv[tt];
        atomicAdd(&g_probsum[e], partial);
    }
    if (tid < NEXP) atomicAdd(&g_cnt[tid], s.scnt[tid]);

    // --- global finalize: last epilogue CTA computes aux loss + resets ---
    __threadfence();
    if (tid == 0) {
        unsigned old = atomicAdd(&g_arrived, 1u);
        s.flag = (old == NTILE - 1);
    }
    __syncthreads();
    if (!s.flag) return;
    __threadfence();

    if (tid < NEXP) {
        float p = __ldcg(&g_probsum[tid]);
        int   c = __ldcg(&g_cnt[tid]);
        s.red[tid] = p * (float)c;
    }
    __syncthreads();
    if (tid == 0) {
        float sacc = 0.0f;
#pragma unroll
        for (int i = 0; i < NEXP; ++i) sacc += s.red[i];
        const float invN = 1.0f / (float)TOKENS;
        out[AUX_OFF] = (float)NEXP * sacc * invN * invN * AUX_W;
        g_arrived = 0u;
    }
    if (tid < NEXP) { g_probsum[tid] = 0.0f; g_cnt[tid] = 0; }
}

extern "C" void kernel_launch(void* const* d_in, const int* in_sizes, int n_in,
                              void* d_out, int out_size) {
    const float* X = (const float*)d_in[0];   // [4,4096,2048] f32
    const float* W = (const float*)d_in[1];   // [64,2048] f32
    float* out = (float*)d_out;               // 65537 f32

    static_assert(sizeof(Smem) <= 80 * 1024, "smem");
    cudaFuncSetAttribute(moe_router, cudaFuncAttributeMaxDynamicSharedMemorySize,
                         (int)sizeof(Smem));
    moe_router<<<NTILE * KSPLIT, NTHR, sizeof(Smem)>>>(X, W, out);
}

// round 12
// speedup vs baseline: 1.2719x; 1.2673x over previous
#include <cuda_runtime.h>
#include <cuda_bf16.h>

// ---------------------------------------------------------------------------
// MoE router, round 11: bf16x3-split GEMM on the tensor pipe via mma.sync
// (HMMA) + ldmatrix — tcgen05 is unavailable at compute_103 in this harness.
//   logits = X @ W^T as 6 bf16 plane-products (fp32-accurate), fp32 accum.
//   Kernel 1: split W[64,2048] into 3 bf16 planes (device scratch).
//   Kernel 2: 128 CTAs x 256 thr. Per CTA: M=128 tok, N=64 exp, K=2048 in 32
//     K=64 slabs. X: LDG->split3->STS SW128; W planes: cp.async SW128.
//     Warp tile 32 tok x 32 exp (4m x 2n warp grid), m16n8k16 fragments.
//   Epilogue: accum -> smem logits, proven top-2/softmax/aux machinery.
// Output f32: [0,32768) indices, [32768,65536) weights, [65536] aux.
// ---------------------------------------------------------------------------

#define TOKENS   16384
#define DDIM     2048
#define NEXP     64
#define BM       128
#define SLABK    64
#define NSLAB    (DDIM / SLABK)     // 32
#define NBLK     (TOKENS / BM)      // 128
#define NTHR     256
#define LSTR     68
#define WGT_OFF  (2 * TOKENS)
#define AUX_OFF  (4 * TOKENS)
#define AUX_W    0.01f

// shared layout (byte offsets from aligned base)
#define OFF_SCNT 0            // 64*4
#define OFF_RED  256          // 64*4
#define OFF_TMAX 512          // 128*4
#define OFF_TINV 1024         // 128*4
#define OFF_FLAG 1536
#define OFF_A    2048         // 3 planes * 128 rows * 128B (SW128) = 49152
#define OFF_B    51200        // 3 planes * 64 rows * 128B  (SW128) = 24576
#define OFF_LOG  2048         // epilogue logits reuse A region (128*68*4)
#define SMEM_REQ 76800

typedef unsigned long long ull;

__device__ __nv_bfloat16 g_wp[3][NEXP][DDIM];   // W planes (768 KB, L2-resident)
__device__ float    g_probsum[NEXP];
__device__ int      g_cnt[NEXP];
__device__ unsigned g_arrived;

__device__ __forceinline__ unsigned su32(const void* p) {
    return (unsigned)__cvta_generic_to_shared(p);
}
__device__ __forceinline__ void cp16(unsigned dst, const void* src) {
    asm volatile("cp.async.cg.shared.global [%0], [%1], 16;" :: "r"(dst), "l"(src));
}
__device__ __forceinline__ void ldsm4(unsigned* r, unsigned addr) {
    asm volatile("ldmatrix.sync.aligned.m8n8.x4.shared.b16 {%0,%1,%2,%3}, [%4];"
                 : "=r"(r[0]), "=r"(r[1]), "=r"(r[2]), "=r"(r[3]) : "r"(addr));
}
__device__ __forceinline__ void mma16816(float* c, const unsigned* a,
                                         unsigned b0, unsigned b1) {
    asm volatile(
        "mma.sync.aligned.m16n8k16.row.col.f32.bf16.bf16.f32 "
        "{%0,%1,%2,%3}, {%4,%5,%6,%7}, {%8,%9}, {%0,%1,%2,%3};"
        : "+f"(c[0]), "+f"(c[1]), "+f"(c[2]), "+f"(c[3])
        : "r"(a[0]), "r"(a[1]), "r"(a[2]), "r"(a[3]), "r"(b0), "r"(b1));
}

__device__ __forceinline__ void split3x2(float2 v, unsigned& q0, unsigned& q1,
                                         unsigned& q2) {
    union { __nv_bfloat162 h; unsigned u; } c0, c1, c2;
    c0.h = __float22bfloat162_rn(v);
    float2 f0 = __bfloat1622float2(c0.h);
    float2 r1 = make_float2(v.x - f0.x, v.y - f0.y);
    c1.h = __float22bfloat162_rn(r1);
    float2 f1 = __bfloat1622float2(c1.h);
    float2 r2 = make_float2(r1.x - f1.x, r1.y - f1.y);
    c2.h = __float22bfloat162_rn(r2);
    q0 = c0.u; q1 = c1.u; q2 = c2.u;
}

// ---------------- kernel 1: split W into bf16 planes ----------------
__global__ void conv_w_kernel(const float* __restrict__ W) {
    int i = blockIdx.x * blockDim.x + threadIdx.x;   // 32768 threads
#pragma unroll
    for (int r = 0; r < 2; ++r) {
        int idx = 2 * i + 65536 * r;                 // pairs: 131072 elems total
        float2 v = *(const float2*)(W + idx);
        unsigned q0, q1, q2;
        split3x2(v, q0, q1, q2);
        int e = idx >> 11, k = idx & 2047;
        *(unsigned*)&g_wp[0][e][k] = q0;
        *(unsigned*)&g_wp[1][e][k] = q1;
        *(unsigned*)&g_wp[2][e][k] = q2;
    }
}

// ---------------- kernel 2: router ----------------
__global__ void __launch_bounds__(NTHR)
router_kernel(const float* __restrict__ X, float* __restrict__ out) {
    extern __shared__ char raw[];
    char* base = raw + ((1024 - ((size_t)raw & 1023)) & 1023);
    const unsigned sb = su32(base);

    const int tid  = threadIdx.x;
    const int lane = tid & 31;
    const int wid  = tid >> 5;
    const int T0   = blockIdx.x * BM;
    const int wm   = wid & 3;          // row group: tokens [wm*32, +32)
    const int wn   = wid >> 2;         // col group: experts [wn*32, +32)

    if (tid < NEXP) ((int*)(base + OFF_SCNT))[tid] = 0;

    // X staging: thread = row*2 + half; 32 floats (8 float4) per slab
    const int xrow  = tid >> 1;
    const int xhalf = tid & 1;
    const float* xptr = X + (size_t)(T0 + xrow) * DDIM + 32 * xhalf;

    // A STS targets (SW128: 16B-chunk index XOR row&7), plane-invariant part
    char* astp[4];
#pragma unroll
    for (int u = 0; u < 4; ++u)
        astp[u] = base + OFF_A + xrow * 128 + (((xhalf * 4 + u) ^ (xrow & 7)) << 4);

    // B cp.async mapping: 6 x 16B chunks per thread per slab
    unsigned    bdst[6];
    const char* bsrc[6];
#pragma unroll
    for (int c = 0; c < 6; ++c) {
        int g = tid + NTHR * c;                    // 0..1535
        int p = g >> 9, rem = g & 511;
        int n = rem >> 3, u = rem & 7;
        bdst[c] = sb + OFF_B + p * 8192 + n * 128 + (((u ^ (n & 7)) << 4));
        bsrc[c] = (const char*)&g_wp[p][n][0] + u * 16;
    }

    // ldmatrix lane addresses
    const int ar   = lane & 15;                    // A row within m16 tile
    unsigned aAddr[2];
#pragma unroll
    for (int mi = 0; mi < 2; ++mi)
        aAddr[mi] = sb + OFF_A + (wm * 32 + mi * 16 + ar) * 128;
    const int aswz = ar & 7;
    const int ak0  = lane >> 4;                    // 16B-unit k offset

    const int br   = (lane & 7) + 8 * (lane >> 4); // B row (expert) within n16
    unsigned bAddr[2];
#pragma unroll
    for (int bt = 0; bt < 2; ++bt)
        bAddr[bt] = sb + OFF_B + (wn * 32 + bt * 16 + br) * 128;
    const int bswz = br & 7;
    const int bk0  = (lane >> 3) & 1;

    float acc[2][4][4];
#pragma unroll
    for (int mi = 0; mi < 2; ++mi)
#pragma unroll
        for (int ni = 0; ni < 4; ++ni)
#pragma unroll
            for (int q = 0; q < 4; ++q) acc[mi][ni][q] = 0.0f;

    // prologue: raw X slab 0
    float4 xr[8];
#pragma unroll
    for (int q = 0; q < 8; ++q) xr[q] = *(const float4*)(xptr + 4 * q);

    const int PA[6] = {0, 0, 1, 1, 0, 2};
    const int PB[6] = {0, 1, 0, 1, 2, 0};

    // ---------------- mainloop: 32 K-slabs ----------------
    for (int it = 0; it < NSLAB; ++it) {
        // B planes for this slab (issue early; overlaps conversion below)
        const int Kb2 = it * SLABK * 2;
#pragma unroll
        for (int c = 0; c < 6; ++c) cp16(bdst[c], bsrc[c] + Kb2);
        asm volatile("cp.async.commit_group;" ::: "memory");

        // split X -> 3 planes, STS (SW128)
        unsigned pk[3][16];
        const float2* xv = (const float2*)xr;
#pragma unroll
        for (int j = 0; j < 16; ++j)
            split3x2(xv[j], pk[0][j], pk[1][j], pk[2][j]);
#pragma unroll
        for (int p = 0; p < 3; ++p)
#pragma unroll
            for (int u = 0; u < 4; ++u)
                *(uint4*)(astp[u] + p * 16384) =
                    make_uint4(pk[p][4*u], pk[p][4*u+1], pk[p][4*u+2], pk[p][4*u+3]);

        asm volatile("cp.async.wait_group 0;" ::: "memory");
        __syncthreads();

        // prefetch next raw X slab (overlaps mma below)
        if (it + 1 < NSLAB) {
            const float* nx = xptr + (it + 1) * SLABK;
#pragma unroll
            for (int q = 0; q < 8; ++q) xr[q] = *(const float4*)(nx + 4 * q);
        }

        // compute: 4 k16 chunks x 6 plane-products x (2m x 4n) mma
#pragma unroll
        for (int c = 0; c < 4; ++c) {
            unsigned af[2][3][4], bf[3][2][4];
#pragma unroll
            for (int mi = 0; mi < 2; ++mi)
#pragma unroll
                for (int p = 0; p < 3; ++p)
                    ldsm4(af[mi][p],
                          aAddr[mi] + p * 16384 + (((2*c + ak0) ^ aswz) << 4));
#pragma unroll
            for (int p = 0; p < 3; ++p)
#pragma unroll
                for (int bt = 0; bt < 2; ++bt)
                    ldsm4(bf[p][bt],
                          bAddr[bt] + p * 8192 + (((2*c + bk0) ^ bswz) << 4));
#pragma unroll
            for (int pp = 0; pp < 6; ++pp) {
                const int pa = PA[pp], pb = PB[pp];
#pragma unroll
                for (int mi = 0; mi < 2; ++mi)
#pragma unroll
                    for (int ni = 0; ni < 4; ++ni)
                        mma16816(acc[mi][ni], af[mi][pa],
                                 bf[pb][ni >> 1][(ni & 1) * 2],
                                 bf[pb][ni >> 1][(ni & 1) * 2 + 1]);
            }
        }
        __syncthreads();
    }

    // ---------------- epilogue ----------------
    float* logits = (float*)(base + OFF_LOG);
    float* tmax   = (float*)(base + OFF_TMAX);
    float* tinv   = (float*)(base + OFF_TINV);
    int*   scnt   = (int*)(base + OFF_SCNT);
    float* red    = (float*)(base + OFF_RED);
    int*   flag   = (int*)(base + OFF_FLAG);

    // accum fragments -> logits smem (frag: c0,c1 = row l/4, cols 2(l&3)+{0,1})
    {
        const int r0 = wm * 32 + (lane >> 2);
        const int c0 = wn * 32 + 2 * (lane & 3);
#pragma unroll
        for (int mi = 0; mi < 2; ++mi)
#pragma unroll
            for (int ni = 0; ni < 4; ++ni) {
                const int rr = r0 + mi * 16, cc = c0 + ni * 8;
                *(float2*)&logits[rr * LSTR + cc] =
                    make_float2(acc[mi][ni][0], acc[mi][ni][1]);
                *(float2*)&logits[(rr + 8) * LSTR + cc] =
                    make_float2(acc[mi][ni][2], acc[mi][ni][3]);
            }
    }
    __syncthreads();

    if (tid < BM) {
        const int t = tid;
        float lg[NEXP];
#pragma unroll
        for (int c = 0; c < NEXP / 4; ++c) {
            float4 v = *(const float4*)&logits[t * LSTR + 4 * c];
            lg[4*c] = v.x; lg[4*c+1] = v.y; lg[4*c+2] = v.z; lg[4*c+3] = v.w;
        }
        // top-2 (stable: strict >, lowest index wins ties) + softmax normalizer
        float m1 = -3.4e38f, m2 = -3.4e38f;
        int   i1 = 0, i2 = 0;
#pragma unroll
        for (int e = 0; e < NEXP; ++e) {
            float l = lg[e];
            if (l > m1) { m2 = m1; i2 = i1; m1 = l; i1 = e; }
            else if (l > m2) { m2 = l; i2 = e; }
        }
        float sum = 0.0f;
#pragma unroll
        for (int e = 0; e < NEXP; ++e) sum += __expf(lg[e] - m1);
        tmax[t] = m1;
        tinv[t] = 1.0f / sum;

        const int T = T0 + t;
        float d  = expf(m2 - m1);
        float w1 = 1.0f / (1.0f + d);
        out[2 * T + 0] = (float)i1;
        out[2 * T + 1] = (float)i2;
        out[WGT_OFF + 2 * T + 0] = w1;
        out[WGT_OFF + 2 * T + 1] = d * w1;

        atomicAdd(&scnt[i1], 1);
    }
    __syncthreads();

    // per-expert probability partials: 4 row-groups x 64 experts x 32 tokens
    {
        const int g  = tid >> 6;
        const int e  = tid & 63;
        const int tb = g * 32;
        float partial = 0.0f;
#pragma unroll 8
        for (int tt = tb; tt < tb + 32; ++tt)
            partial += __expf(logits[tt * LSTR + e] - tmax[tt]) * tinv[tt];
        atomicAdd(&g_probsum[e], partial);
    }
    if (tid < NEXP) atomicAdd(&g_cnt[tid], scnt[tid]);

    // --- global finalize: last CTA computes aux loss + resets state ---
    __threadfence();
    if (tid == 0) {
        unsigned old = atomicAdd(&g_arrived, 1u);
        *flag = (old == NBLK - 1);
    }
    __syncthreads();
    if (!*flag) return;
    __threadfence();

    if (tid < NEXP) {
        float p = __ldcg(&g_probsum[tid]);
        int   c = __ldcg(&g_cnt[tid]);
        red[tid] = p * (float)c;
    }
    __syncthreads();
    if (tid == 0) {
        float sacc = 0.0f;
#pragma unroll
        for (int i = 0; i < NEXP; ++i) sacc += red[i];
        const float invN = 1.0f / (float)TOKENS;
        out[AUX_OFF] = (float)NEXP * sacc * invN * invN * AUX_W;
        g_arrived = 0u;
    }
    if (tid < NEXP) { g_probsum[tid] = 0.0f; g_cnt[tid] = 0; }
}

extern "C" void kernel_launch(void* const* d_in, const int* in_sizes, int n_in,
                              void* d_out, int out_size) {
    const float* X = (const float*)d_in[0];   // [4,4096,2048] f32
    const float* W = (const float*)d_in[1];   // [64,2048] f32
    float* out = (float*)d_out;               // 65537 f32

    cudaFuncSetAttribute(router_kernel,
                         cudaFuncAttributeMaxDynamicSharedMemorySize, SMEM_REQ);
    conv_w_kernel<<<64, 512>>>(W);
    router_kernel<<<NBLK, NTHR, SMEM_REQ>>>(X, out);
}

// round 15
// speedup vs baseline: 1.2953x; 1.0184x over previous
#include <cuda_runtime.h>
#include <cuda_fp16.h>

// ---------------------------------------------------------------------------
// MoE router, round 13: fp16 2-plane split GEMM on tensor pipe (mma.sync).
//   logits = X @ W^T via 3 fp16 plane-products (h0w0, h0w1, h1w0): dropped
//   term h1w1 ~ 2^-24 — same error as the passing bf16 6-product kernel.
//   Kernel 1: split W[64,2048] into 2 fp16 planes.
//   Kernel 2: 128 CTAs x 256 thr; M=128 tok, N=64 exp, K=2048 in 32 slabs.
//     DOUBLE-BUFFERED A/B tiles, ONE barrier per slab: convert/STS(i+1) and
//     cp.async B(i+1) overlap MMA(i). Warp tile 32x32, m16n8k16 fragments.
//   Epilogue: proven top-2/softmax/aux machinery (unchanged from round 11).
// Output f32: [0,32768) indices, [32768,65536) weights, [65536] aux.
// ---------------------------------------------------------------------------

#define TOKENS   16384
#define DDIM     2048
#define NEXP     64
#define BM       128
#define SLABK    64
#define NSLAB    (DDIM / SLABK)     // 32
#define NBLK     (TOKENS / BM)      // 128
#define NTHR     256
#define LSTR     68
#define WGT_OFF  (2 * TOKENS)
#define AUX_OFF  (4 * TOKENS)
#define AUX_W    0.01f

// shared layout (byte offsets from aligned base)
#define OFF_SCNT 0            // 64*4
#define OFF_RED  256          // 64*4
#define OFF_TMAX 512          // 128*4
#define OFF_TINV 1024         // 128*4
#define OFF_FLAG 1536
#define OFF_A    2048         // 2 bufs x 2 planes x 16384 = 65536
#define ABUF     32768
#define APLN     16384
#define OFF_B    67584        // 2 bufs x 2 planes x 8192  = 32768
#define BBUF     16384
#define BPLN     8192
#define OFF_LOG  2048         // epilogue logits reuse A region (128*68*4)
#define SMEM_REQ 101376

typedef unsigned long long ull;

__device__ __half   g_wp[2][NEXP][DDIM];        // W planes (512 KB, L2-resident)
__device__ float    g_probsum[NEXP];
__device__ int      g_cnt[NEXP];
__device__ unsigned g_arrived;

__device__ __forceinline__ unsigned su32(const void* p) {
    return (unsigned)__cvta_generic_to_shared(p);
}
__device__ __forceinline__ void cp16(unsigned dst, const void* src) {
    asm volatile("cp.async.cg.shared.global [%0], [%1], 16;" :: "r"(dst), "l"(src));
}
__device__ __forceinline__ void ldsm4(unsigned* r, unsigned addr) {
    asm volatile("ldmatrix.sync.aligned.m8n8.x4.shared.b16 {%0,%1,%2,%3}, [%4];"
                 : "=r"(r[0]), "=r"(r[1]), "=r"(r[2]), "=r"(r[3]) : "r"(addr));
}
__device__ __forceinline__ void mma16816(float* c, const unsigned* a,
                                         unsigned b0, unsigned b1) {
    asm volatile(
        "mma.sync.aligned.m16n8k16.row.col.f32.f16.f16.f32 "
        "{%0,%1,%2,%3}, {%4,%5,%6,%7}, {%8,%9}, {%0,%1,%2,%3};"
        : "+f"(c[0]), "+f"(c[1]), "+f"(c[2]), "+f"(c[3])
        : "r"(a[0]), "r"(a[1]), "r"(a[2]), "r"(a[3]), "r"(b0), "r"(b1));
}

__device__ __forceinline__ void split2x2(float2 v, unsigned& q0, unsigned& q1) {
    union { __half2 h; unsigned u; } c0, c1;
    c0.h = __float22half2_rn(v);
    float2 f0 = __half22float2(c0.h);
    c1.h = __float22half2_rn(make_float2(v.x - f0.x, v.y - f0.y));
    q0 = c0.u; q1 = c1.u;
}

// ---------------- kernel 1: split W into 2 fp16 planes ----------------
__global__ void conv_w_kernel(const float* __restrict__ W) {
    int i = blockIdx.x * blockDim.x + threadIdx.x;   // 32768 threads
#pragma unroll
    for (int r = 0; r < 2; ++r) {
        int idx = 2 * i + 65536 * r;                 // 65536 pairs total
        float2 v = *(const float2*)(W + idx);
        unsigned q0, q1;
        split2x2(v, q0, q1);
        int e = idx >> 11, k = idx & 2047;
        *(unsigned*)&g_wp[0][e][k] = q0;
        *(unsigned*)&g_wp[1][e][k] = q1;
    }
}

// ---------------- kernel 2: router ----------------
__global__ void __launch_bounds__(NTHR)
router_kernel(const float* __restrict__ X, float* __restrict__ out) {
    extern __shared__ char raw[];
    char* base = raw + ((1024 - ((size_t)raw & 1023)) & 1023);
    const unsigned sb = su32(base);

    const int tid  = threadIdx.x;
    const int lane = tid & 31;
    const int wid  = tid >> 5;
    const int T0   = blockIdx.x * BM;
    const int wm   = wid & 3;          // row group: tokens [wm*32, +32)
    const int wn   = wid >> 2;         // col group: experts [wn*32, +32)

    if (tid < NEXP) ((int*)(base + OFF_SCNT))[tid] = 0;

    // X staging: thread = row*2 + half; 32 floats (8 float4) per slab
    const int xrow  = tid >> 1;
    const int xhalf = tid & 1;
    const float* xptr = X + (size_t)(T0 + xrow) * DDIM + 32 * xhalf;

    // A STS targets (SW128), buf/plane added per use
    char* astp[4];
#pragma unroll
    for (int u = 0; u < 4; ++u)
        astp[u] = base + OFF_A + xrow * 128 + (((xhalf * 4 + u) ^ (xrow & 7)) << 4);

    // B cp.async mapping: 4 x 16B chunks per thread per slab (2 planes x 512)
    unsigned    bdst[4];
    const char* bsrc[4];
#pragma unroll
    for (int c = 0; c < 4; ++c) {
        int g = tid + NTHR * c;                    // 0..1023
        int p = g >> 9, rem = g & 511;
        int n = rem >> 3, u = rem & 7;
        bdst[c] = sb + OFF_B + p * BPLN + n * 128 + ((u ^ (n & 7)) << 4);
        bsrc[c] = (const char*)&g_wp[p][n][0] + u * 16;
    }

    // ldmatrix lane addresses (buf/plane/chunk added per use)
    const int ar   = lane & 15;
    unsigned aAddr[2];
#pragma unroll
    for (int mi = 0; mi < 2; ++mi)
        aAddr[mi] = sb + OFF_A + (wm * 32 + mi * 16 + ar) * 128;
    const int aswz = ar & 7;
    const int ak0  = lane >> 4;

    const int br   = (lane & 7) + 8 * (lane >> 4);
    unsigned bAddr[2];
#pragma unroll
    for (int bt = 0; bt < 2; ++bt)
        bAddr[bt] = sb + OFF_B + (wn * 32 + bt * 16 + br) * 128;
    const int bswz = br & 7;
    const int bk0  = (lane >> 3) & 1;

    float acc[2][4][4];
#pragma unroll
    for (int mi = 0; mi < 2; ++mi)
#pragma unroll
        for (int ni = 0; ni < 4; ++ni)
#pragma unroll
            for (int q = 0; q < 4; ++q) acc[mi][ni][q] = 0.0f;

    const int PA[3] = {0, 0, 1};
    const int PB[3] = {0, 1, 0};

    // ---------------- prologue: stage slab 0 into buf 0 ----------------
    float4 xr[8];
#pragma unroll
    for (int q = 0; q < 8; ++q) xr[q] = *(const float4*)(xptr + 4 * q);
#pragma unroll
    for (int c = 0; c < 4; ++c) cp16(bdst[c], bsrc[c]);
    asm volatile("cp.async.commit_group;" ::: "memory");
    {
        unsigned pk[2][16];
        const float2* xv = (const float2*)xr;
#pragma unroll
        for (int j = 0; j < 16; ++j) split2x2(xv[j], pk[0][j], pk[1][j]);
#pragma unroll
        for (int p = 0; p < 2; ++p)
#pragma unroll
            for (int u = 0; u < 4; ++u)
                *(uint4*)(astp[u] + p * APLN) =
                    make_uint4(pk[p][4*u], pk[p][4*u+1], pk[p][4*u+2], pk[p][4*u+3]);
    }
    asm volatile("cp.async.wait_group 0;" ::: "memory");
    __syncthreads();

    // ---------------- mainloop: 32 K-slabs, double-buffered ----------------
    for (int it = 0; it < NSLAB; ++it) {
        const int buf  = it & 1;
        const int nbuf = buf ^ 1;

        if (it + 1 < NSLAB) {
            // prefetch raw X(i+1) and launch B(i+1) into the other buffer
            const float* nx = xptr + (it + 1) * SLABK;
#pragma unroll
            for (int q = 0; q < 8; ++q) xr[q] = *(const float4*)(nx + 4 * q);
            const int Kb2 = (it + 1) * SLABK * 2;
#pragma unroll
            for (int c = 0; c < 4; ++c)
                cp16(bdst[c] + nbuf * BBUF, bsrc[c] + Kb2);
            asm volatile("cp.async.commit_group;" ::: "memory");
        }

        // MMA(i) from buf: 4 k16 chunks x 3 plane-products x (2m x 4n)
#pragma unroll
        for (int c = 0; c < 4; ++c) {
            unsigned af[2][2][4], bf[2][2][4];
#pragma unroll
            for (int mi = 0; mi < 2; ++mi)
#pragma unroll
                for (int p = 0; p < 2; ++p)
                    ldsm4(af[mi][p], aAddr[mi] + buf * ABUF + p * APLN +
                                     (((2*c + ak0) ^ aswz) << 4));
#pragma unroll
            for (int p = 0; p < 2; ++p)
#pragma unroll
                for (int bt = 0; bt < 2; ++bt)
                    ldsm4(bf[p][bt], bAddr[bt] + buf * BBUF + p * BPLN +
                                     (((2*c + bk0) ^ bswz) << 4));
#pragma unroll
            for (int pp = 0; pp < 3; ++pp) {
                const int pa = PA[pp], pb = PB[pp];
#pragma unroll
                for (int mi = 0; mi < 2; ++mi)
#pragma unroll
                    for (int ni = 0; ni < 4; ++ni)
                        mma16816(acc[mi][ni], af[mi][pa],
                                 bf[pb][ni >> 1][(ni & 1) * 2],
                                 bf[pb][ni >> 1][(ni & 1) * 2 + 1]);
            }
        }

        if (it + 1 < NSLAB) {
            // convert + STS A(i+1) into the other buffer (overlaps MMA above)
            unsigned pk[2][16];
            const float2* xv = (const float2*)xr;
#pragma unroll
            for (int j = 0; j < 16; ++j) split2x2(xv[j], pk[0][j], pk[1][j]);
#pragma unroll
            for (int p = 0; p < 2; ++p)
#pragma unroll
                for (int u = 0; u < 4; ++u)
                    *(uint4*)(astp[u] + nbuf * ABUF + p * APLN) =
                        make_uint4(pk[p][4*u], pk[p][4*u+1],
                                   pk[p][4*u+2], pk[p][4*u+3]);
            asm volatile("cp.async.wait_group 0;" ::: "memory");
        }
        __syncthreads();
    }

    // ---------------- epilogue ----------------
    float* logits = (float*)(base + OFF_LOG);
    float* tmax   = (float*)(base + OFF_TMAX);
    float* tinv   = (float*)(base + OFF_TINV);
    int*   scnt   = (int*)(base + OFF_SCNT);
    float* red    = (float*)(base + OFF_RED);
    int*   flag   = (int*)(base + OFF_FLAG);

    // accum fragments -> logits smem
    {
        const int r0 = wm * 32 + (lane >> 2);
        const int c0 = wn * 32 + 2 * (lane & 3);
#pragma unroll
        for (int mi = 0; mi < 2; ++mi)
#pragma unroll
            for (int ni = 0; ni < 4; ++ni) {
                const int rr = r0 + mi * 16, cc = c0 + ni * 8;
                *(float2*)&logits[rr * LSTR + cc] =
                    make_float2(acc[mi][ni][0], acc[mi][ni][1]);
                *(float2*)&logits[(rr + 8) * LSTR + cc] =
                    make_float2(acc[mi][ni][2], acc[mi][ni][3]);
            }
    }
    __syncthreads();

    if (tid < BM) {
        const int t = tid;
        float lg[NEXP];
#pragma unroll
        for (int c = 0; c < NEXP / 4; ++c) {
            float4 v = *(const float4*)&logits[t * LSTR + 4 * c];
            lg[4*c] = v.x; lg[4*c+1] = v.y; lg[4*c+2] = v.z; lg[4*c+3] = v.w;
        }
        // top-2 (stable: strict >, lowest index wins ties) + softmax normalizer
        float m1 = -3.4e38f, m2 = -3.4e38f;
        int   i1 = 0, i2 = 0;
#pragma unroll
        for (int e = 0; e < NEXP; ++e) {
            float l = lg[e];
            if (l > m1) { m2 = m1; i2 = i1; m1 = l; i1 = e; }
            else if (l > m2) { m2 = l; i2 = e; }
        }
        float sum = 0.0f;
#pragma unroll
        for (int e = 0; e < NEXP; ++e) sum += __expf(lg[e] - m1);
        tmax[t] = m1;
        tinv[t] = 1.0f / sum;

        const int T = T0 + t;
        float d  = expf(m2 - m1);
        float w1 = 1.0f / (1.0f + d);
        out[2 * T + 0] = (float)i1;
        out[2 * T + 1] = (float)i2;
        out[WGT_OFF + 2 * T + 0] = w1;
        out[WGT_OFF + 2 * T + 1] = d * w1;

        atomicAdd(&scnt[i1], 1);
    }
    __syncthreads();

    // per-expert probability partials: 4 row-groups x 64 experts x 32 tokens
    {
        const int g  = tid >> 6;
        const int e  = tid & 63;
        const int tb = g * 32;
        float partial = 0.0f;
#pragma unroll 8
        for (int tt = tb; tt < tb + 32; ++tt)
            partial += __expf(logits[tt * LSTR + e] - tmax[tt]) * tinv[tt];
        atomicAdd(&g_probsum[e], partial);
    }
    if (tid < NEXP) atomicAdd(&g_cnt[tid], scnt[tid]);

    // --- global finalize: last CTA computes aux loss + resets state ---
    __threadfence();
    if (tid == 0) {
        unsigned old = atomicAdd(&g_arrived, 1u);
        *flag = (old == NBLK - 1);
    }
    __syncthreads();
    if (!*flag) return;
    __threadfence();

    if (tid < NEXP) {
        float p = __ldcg(&g_probsum[tid]);
        int   c = __ldcg(&g_cnt[tid]);
        red[tid] = p * (float)c;
    }
    __syncthreads();
    if (tid == 0) {
        float sacc = 0.0f;
#pragma unroll
        for (int i = 0; i < NEXP; ++i) sacc += red[i];
        const float invN = 1.0f / (float)TOKENS;
        out[AUX_OFF] = (float)NEXP * sacc * invN * invN * AUX_W;
        g_arrived = 0u;
    }
    if (tid < NEXP) { g_probsum[tid] = 0.0f; g_cnt[tid] = 0; }
}

extern "C" void kernel_launch(void* const* d_in, const int* in_sizes, int n_in,
                              void* d_out, int out_size) {
    const float* X = (const float*)d_in[0];   // [4,4096,2048] f32
    const float* W = (const float*)d_in[1];   // [64,2048] f32
    float* out = (float*)d_out;               // 65537 f32

    cudaFuncSetAttribute(router_kernel,
                         cudaFuncAttributeMaxDynamicSharedMemorySize, SMEM_REQ);
    conv_w_kernel<<<64, 512>>>(W);
    router_kernel<<<NBLK, NTHR, SMEM_REQ>>>(X, out);
}

// round 16
// speedup vs baseline: 1.8923x; 1.4609x over previous
#include <cuda_runtime.h>
#include <cuda_fp16.h>

// ---------------------------------------------------------------------------
// MoE router, round 16: fp16 2-plane split GEMM (mma.sync), 16 warps/CTA.
//   logits = X @ W^T via 3 fp16 plane-products (h0w0, h0w1, h1w0).
//   Kernel 1: split W[64,2048] into 2 fp16 planes.
//   Kernel 2: 128 CTAs x 512 thr; M=128 tok, N=64 exp, K=2048 in 32 slabs.
//     Warp grid 4m x 4n (warp tile 32x16). Double-buffered A/B, one barrier
//     per slab; convert/STS(i+1) + cp.async B(i+1) overlap MMA(i).
//   Epilogue: proven top-2/softmax/aux machinery.
// Output f32: [0,32768) indices, [32768,65536) weights, [65536] aux.
// ---------------------------------------------------------------------------

#define TOKENS   16384
#define DDIM     2048
#define NEXP     64
#define BM       128
#define SLABK    64
#define NSLAB    (DDIM / SLABK)     // 32
#define NBLK     (TOKENS / BM)      // 128
#define NTHR     512
#define LSTR     68
#define WGT_OFF  (2 * TOKENS)
#define AUX_OFF  (4 * TOKENS)
#define AUX_W    0.01f

// shared layout (byte offsets from aligned base)
#define OFF_SCNT 0            // 64*4
#define OFF_RED  256          // 64*4
#define OFF_TMAX 512          // 128*4
#define OFF_TINV 1024         // 128*4
#define OFF_FLAG 1536
#define OFF_A    2048         // 2 bufs x 2 planes x 16384 = 65536
#define ABUF     32768
#define APLN     16384
#define OFF_B    67584        // 2 bufs x 2 planes x 8192  = 32768
#define BBUF     16384
#define BPLN     8192
#define OFF_LOG  2048         // epilogue logits reuse A region (128*68*4)
#define SMEM_REQ 101376

typedef unsigned long long ull;

__device__ __half   g_wp[2][NEXP][DDIM];        // W planes (512 KB, L2-resident)
__device__ float    g_probsum[NEXP];
__device__ int      g_cnt[NEXP];
__device__ unsigned g_arrived;

__device__ __forceinline__ unsigned su32(const void* p) {
    return (unsigned)__cvta_generic_to_shared(p);
}
__device__ __forceinline__ void cp16(unsigned dst, const void* src) {
    asm volatile("cp.async.cg.shared.global [%0], [%1], 16;" :: "r"(dst), "l"(src));
}
__device__ __forceinline__ void ldsm4(unsigned* r, unsigned addr) {
    asm volatile("ldmatrix.sync.aligned.m8n8.x4.shared.b16 {%0,%1,%2,%3}, [%4];"
                 : "=r"(r[0]), "=r"(r[1]), "=r"(r[2]), "=r"(r[3]) : "r"(addr));
}
__device__ __forceinline__ void mma16816(float* c, const unsigned* a,
                                         unsigned b0, unsigned b1) {
    asm volatile(
        "mma.sync.aligned.m16n8k16.row.col.f32.f16.f16.f32 "
        "{%0,%1,%2,%3}, {%4,%5,%6,%7}, {%8,%9}, {%0,%1,%2,%3};"
        : "+f"(c[0]), "+f"(c[1]), "+f"(c[2]), "+f"(c[3])
        : "r"(a[0]), "r"(a[1]), "r"(a[2]), "r"(a[3]), "r"(b0), "r"(b1));
}

__device__ __forceinline__ void split2x2(float2 v, unsigned& q0, unsigned& q1) {
    union { __half2 h; unsigned u; } c0, c1;
    c0.h = __float22half2_rn(v);
    float2 f0 = __half22float2(c0.h);
    c1.h = __float22half2_rn(make_float2(v.x - f0.x, v.y - f0.y));
    q0 = c0.u; q1 = c1.u;
}

// ---------------- kernel 1: split W into 2 fp16 planes ----------------
__global__ void conv_w_kernel(const float* __restrict__ W) {
    int i = blockIdx.x * blockDim.x + threadIdx.x;   // 32768 threads
#pragma unroll
    for (int r = 0; r < 2; ++r) {
        int idx = 2 * i + 65536 * r;                 // 65536 pairs total
        float2 v = *(const float2*)(W + idx);
        unsigned q0, q1;
        split2x2(v, q0, q1);
        int e = idx >> 11, k = idx & 2047;
        *(unsigned*)&g_wp[0][e][k] = q0;
        *(unsigned*)&g_wp[1][e][k] = q1;
    }
}

// ---------------- kernel 2: router ----------------
__global__ void __launch_bounds__(NTHR)
router_kernel(const float* __restrict__ X, float* __restrict__ out) {
    extern __shared__ char raw[];
    char* base = raw + ((1024 - ((size_t)raw & 1023)) & 1023);
    const unsigned sb = su32(base);

    const int tid  = threadIdx.x;
    const int lane = tid & 31;
    const int wid  = tid >> 5;          // 0..15
    const int T0   = blockIdx.x * BM;
    const int wm   = wid & 3;           // token group [wm*32, +32)
    const int wn   = wid >> 2;          // expert group [wn*16, +16)

    if (tid < NEXP) ((int*)(base + OFF_SCNT))[tid] = 0;

    // X staging: thread = row*4 + quarter; 16 floats (4 float4) per slab
    const int xrow = tid >> 2;          // 0..127
    const int xq   = tid & 3;           // 16-float quarter
    const float* xptr = X + (size_t)(T0 + xrow) * DDIM + 16 * xq;

    // A STS targets (SW128): 2 chunks of 16B per plane (u = 2*xq, 2*xq+1)
    char* astp[2];
#pragma unroll
    for (int u = 0; u < 2; ++u)
        astp[u] = base + OFF_A + xrow * 128 +
                  (((2 * xq + u) ^ (xrow & 7)) << 4);

    // B cp.async mapping: 2 x 16B chunks per thread per slab (2 planes x 512)
    unsigned    bdst[2];
    const char* bsrc[2];
#pragma unroll
    for (int c = 0; c < 2; ++c) {
        int g = tid + NTHR * c;                    // 0..1023
        int p = g >> 9, rem = g & 511;
        int n = rem >> 3, u = rem & 7;
        bdst[c] = sb + OFF_B + p * BPLN + n * 128 + ((u ^ (n & 7)) << 4);
        bsrc[c] = (const char*)&g_wp[p][n][0] + u * 16;
    }

    // ldmatrix lane addresses
    const int ar   = lane & 15;
    unsigned aAddr[2];
#pragma unroll
    for (int mi = 0; mi < 2; ++mi)
        aAddr[mi] = sb + OFF_A + (wm * 32 + mi * 16 + ar) * 128;
    const int aswz = ar & 7;
    const int ak0  = lane >> 4;

    const int br   = (lane & 7) + 8 * (lane >> 4);   // expert row within n16
    const unsigned bAddr = sb + OFF_B + (wn * 16 + br) * 128;
    const int bswz = br & 7;
    const int bk0  = (lane >> 3) & 1;

    float acc[2][2][4];
#pragma unroll
    for (int mi = 0; mi < 2; ++mi)
#pragma unroll
        for (int ni = 0; ni < 2; ++ni)
#pragma unroll
            for (int q = 0; q < 4; ++q) acc[mi][ni][q] = 0.0f;

    const int PA[3] = {0, 0, 1};
    const int PB[3] = {0, 1, 0};

    // ---------------- prologue: stage slab 0 into buf 0 ----------------
    float4 xr[4];
#pragma unroll
    for (int q = 0; q < 4; ++q) xr[q] = *(const float4*)(xptr + 4 * q);
#pragma unroll
    for (int c = 0; c < 2; ++c) cp16(bdst[c], bsrc[c]);
    asm volatile("cp.async.commit_group;" ::: "memory");
    {
        unsigned pk[2][8];
        const float2* xv = (const float2*)xr;
#pragma unroll
        for (int j = 0; j < 8; ++j) split2x2(xv[j], pk[0][j], pk[1][j]);
#pragma unroll
        for (int p = 0; p < 2; ++p)
#pragma unroll
            for (int u = 0; u < 2; ++u)
                *(uint4*)(astp[u] + p * APLN) =
                    make_uint4(pk[p][4*u], pk[p][4*u+1], pk[p][4*u+2], pk[p][4*u+3]);
    }
    asm volatile("cp.async.wait_group 0;" ::: "memory");
    __syncthreads();

    // ---------------- mainloop: 32 K-slabs, double-buffered ----------------
    for (int it = 0; it < NSLAB; ++it) {
        const int buf  = it & 1;
        const int nbuf = buf ^ 1;

        if (it + 1 < NSLAB) {
            const float* nx = xptr + (it + 1) * SLABK;
#pragma unroll
            for (int q = 0; q < 4; ++q) xr[q] = *(const float4*)(nx + 4 * q);
            const int Kb2 = (it + 1) * SLABK * 2;
#pragma unroll
            for (int c = 0; c < 2; ++c)
                cp16(bdst[c] + nbuf * BBUF, bsrc[c] + Kb2);
            asm volatile("cp.async.commit_group;" ::: "memory");
        }

        // MMA(i): 4 k16 chunks x 3 plane-products x (2m x 2n)
#pragma unroll
        for (int c = 0; c < 4; ++c) {
            unsigned af[2][2][4], bf[2][4];
#pragma unroll
            for (int mi = 0; mi < 2; ++mi)
#pragma unroll
                for (int p = 0; p < 2; ++p)
                    ldsm4(af[mi][p], aAddr[mi] + buf * ABUF + p * APLN +
                                     (((2*c + ak0) ^ aswz) << 4));
#pragma unroll
            for (int p = 0; p < 2; ++p)
                ldsm4(bf[p], bAddr + buf * BBUF + p * BPLN +
                             (((2*c + bk0) ^ bswz) << 4));
#pragma unroll
            for (int pp = 0; pp < 3; ++pp) {
                const int pa = PA[pp], pb = PB[pp];
#pragma unroll
                for (int mi = 0; mi < 2; ++mi)
#pragma unroll
                    for (int ni = 0; ni < 2; ++ni)
                        mma16816(acc[mi][ni], af[mi][pa],
                                 bf[pb][2 * ni], bf[pb][2 * ni + 1]);
            }
        }

        if (it + 1 < NSLAB) {
            // convert + STS A(i+1) (overlaps MMA latency above)
            unsigned pk[2][8];
            const float2* xv = (const float2*)xr;
#pragma unroll
            for (int j = 0; j < 8; ++j) split2x2(xv[j], pk[0][j], pk[1][j]);
#pragma unroll
            for (int p = 0; p < 2; ++p)
#pragma unroll
                for (int u = 0; u < 2; ++u)
                    *(uint4*)(astp[u] + nbuf * ABUF + p * APLN) =
                        make_uint4(pk[p][4*u], pk[p][4*u+1],
                                   pk[p][4*u+2], pk[p][4*u+3]);
            asm volatile("cp.async.wait_group 0;" ::: "memory");
        }
        __syncthreads();
    }

    // ---------------- epilogue ----------------
    float* logits = (float*)(base + OFF_LOG);
    float* tmax   = (float*)(base + OFF_TMAX);
    float* tinv   = (float*)(base + OFF_TINV);
    int*   scnt   = (int*)(base + OFF_SCNT);
    float* red    = (float*)(base + OFF_RED);
    int*   flag   = (int*)(base + OFF_FLAG);

    // accum fragments -> logits smem
    {
        const int r0 = wm * 32 + (lane >> 2);
        const int c0 = wn * 16 + 2 * (lane & 3);
#pragma unroll
        for (int mi = 0; mi < 2; ++mi)
#pragma unroll
            for (int ni = 0; ni < 2; ++ni) {
                const int rr = r0 + mi * 16, cc = c0 + ni * 8;
                *(float2*)&logits[rr * LSTR + cc] =
                    make_float2(acc[mi][ni][0], acc[mi][ni][1]);
                *(float2*)&logits[(rr + 8) * LSTR + cc] =
                    make_float2(acc[mi][ni][2], acc[mi][ni][3]);
            }
    }
    __syncthreads();

    if (tid < BM) {
        const int t = tid;
        float lg[NEXP];
#pragma unroll
        for (int c = 0; c < NEXP / 4; ++c) {
            float4 v = *(const float4*)&logits[t * LSTR + 4 * c];
            lg[4*c] = v.x; lg[4*c+1] = v.y; lg[4*c+2] = v.z; lg[4*c+3] = v.w;
        }
        // top-2 (stable: strict >, lowest index wins ties) + softmax normalizer
        float m1 = -3.4e38f, m2 = -3.4e38f;
        int   i1 = 0, i2 = 0;
#pragma unroll
        for (int e = 0; e < NEXP; ++e) {
            float l = lg[e];
            if (l > m1) { m2 = m1; i2 = i1; m1 = l; i1 = e; }
            else if (l > m2) { m2 = l; i2 = e; }
        }
        float sum = 0.0f;
#pragma unroll
        for (int e = 0; e < NEXP; ++e) sum += __expf(lg[e] - m1);
        tmax[t] = m1;
        tinv[t] = 1.0f / sum;

        const int T = T0 + t;
        float d  = expf(m2 - m1);
        float w1 = 1.0f / (1.0f + d);
        out[2 * T + 0] = (float)i1;
        out[2 * T + 1] = (float)i2;
        out[WGT_OFF + 2 * T + 0] = w1;
        out[WGT_OFF + 2 * T + 1] = d * w1;

        atomicAdd(&scnt[i1], 1);
    }
    __syncthreads();

    // per-expert probability partials: 8 row-groups x 64 experts x 16 tokens
    {
        const int g  = tid >> 6;            // 0..7
        const int e  = tid & 63;
        const int tb = g * 16;
        float partial = 0.0f;
#pragma unroll 8
        for (int tt = tb; tt < tb + 16; ++tt)
            partial += __expf(logits[tt * LSTR + e] - tmax[tt]) * tinv[tt];
        atomicAdd(&g_probsum[e], partial);
    }
    if (tid < NEXP) atomicAdd(&g_cnt[tid], scnt[tid]);

    // --- global finalize: last CTA computes aux loss + resets state ---
    __threadfence();
    if (tid == 0) {
        unsigned old = atomicAdd(&g_arrived, 1u);
        *flag = (old == NBLK - 1);
    }
    __syncthreads();
    if (!*flag) return;
    __threadfence();

    if (tid < NEXP) {
        float p = __ldcg(&g_probsum[tid]);
        int   c = __ldcg(&g_cnt[tid]);
        red[tid] = p * (float)c;
    }
    __syncthreads();
    if (tid == 0) {
        float sacc = 0.0f;
#pragma unroll
        for (int i = 0; i < NEXP; ++i) sacc += red[i];
        const float invN = 1.0f / (float)TOKENS;
        out[AUX_OFF] = (float)NEXP * sacc * invN * invN * AUX_W;
        g_arrived = 0u;
    }
    if (tid < NEXP) { g_probsum[tid] = 0.0f; g_cnt[tid] = 0; }
}

extern "C" void kernel_launch(void* const* d_in, const int* in_sizes, int n_in,
                              void* d_out, int out_size) {
    const float* X = (const float*)d_in[0];   // [4,4096,2048] f32
    const float* W = (const float*)d_in[1];   // [64,2048] f32
    float* out = (float*)d_out;               // 65537 f32

    cudaFuncSetAttribute(router_kernel,
                         cudaFuncAttributeMaxDynamicSharedMemorySize, SMEM_REQ);
    conv_w_kernel<<<64, 512>>>(W);
    router_kernel<<<NBLK, NTHR, SMEM_REQ>>>(X, out);
}